// round 6
// baseline (speedup 1.0000x reference)
#include <cuda_runtime.h>
#include <cuda_fp16.h>
#include <math.h>

#define NT 2000
#define NPT 255
#define NC 16
#define NM 32
#define NG 16

typedef unsigned long long ull;

// w pairsum region: EXACT R4 layout (slot = [g][c], 256 floats, unpadded)
#define W_R0 0                         // 32 slots (written by levels 6,4,2)
#define W_R1 (32*256)                  // 16 slots (written by levels 5,3,1)
#define W_FLOATS (48*256)              // 49152 B
// emission table: [m][g][c] fp32 (R4 layout)
#define BF_FLOATS (NM*NG*NC)           // 32768 B
// normalized leaf-beta table: half, g-stride 20 halfs (40B, conflict-free + 8B aligned)
#define LSTR 20
#define LEAF_HALFS (NM*NG*LSTR)        // 20480 B
#define NUL_FLOATS (NM*NG)             // 2048 B
#define DYN_BYTES (W_FLOATS*4 + BF_FLOATS*4 + LEAF_HALFS*2 + NUL_FLOATS*4)  // 104448

__device__ float  g_smA[NC*NC*NG];     // softmaxed A, [p][c][g]
__device__ float  g_smBf[NM*NG*NC];    // softmaxed B, [m][g][c]
__device__ float  g_smPi[NC*NG];       // softmaxed Pi, [c][g]
__device__ __half g_leafH[NM*NG*NC];   // Pi*B/nu, [m][g][c]
__device__ float  g_nuLog[NM*NG];      // log2 nu per (m,g)

// ---------------------------------------------------------------------------
// packed f32x2 helpers
// ---------------------------------------------------------------------------
__device__ __forceinline__ ull pack2(float lo, float hi) {
    ull r; asm("mov.b64 %0, {%1, %2};" : "=l"(r) : "f"(lo), "f"(hi)); return r;
}
__device__ __forceinline__ void ffma2(ull& d, ull a, ull b) {
    asm("fma.rn.f32x2 %0, %1, %2, %0;" : "+l"(d) : "l"(a), "l"(b));
}
__device__ __forceinline__ float unpack_sum(ull v) {
    float lo, hi; asm("mov.b64 {%0, %1}, %2;" : "=f"(lo), "=f"(hi) : "l"(v));
    return lo + hi;
}
__device__ __forceinline__ ull h2sum_to_f32x2(unsigned ha, unsigned hb) {
    __half2 s = __hadd2(*(__half2*)&ha, *(__half2*)&hb);
    float2 f = __half22float2(s);
    return pack2(f.x, f.y);
}

// ---------------------------------------------------------------------------
// Prologue: softmaxes + emission table + normalized-leaf table + log nu.
// 1 block, 256 threads.
// ---------------------------------------------------------------------------
__global__ void htmm_softmax_kernel(const float* __restrict__ A,
                                    const float* __restrict__ B,
                                    const float* __restrict__ Pi) {
    int tid = threadIdx.x;
    int c = tid >> 4;
    int g = tid & 15;
    {   // A: softmax over p for each (c,g)
        float mx = -1e30f;
        #pragma unroll
        for (int p = 0; p < NC; p++) mx = fmaxf(mx, A[p*NC*NG + c*NG + g]);
        float e[NC]; float s = 0.f;
        #pragma unroll
        for (int p = 0; p < NC; p++) { e[p] = expf(A[p*NC*NG + c*NG + g] - mx); s += e[p]; }
        float rs = 1.f / s;
        #pragma unroll
        for (int p = 0; p < NC; p++) g_smA[p*NC*NG + c*NG + g] = e[p] * rs;
    }
    {   // B: softmax over m for each (c,g); store [m][g][c]
        float mx = -1e30f;
        #pragma unroll
        for (int m = 0; m < NM; m++) mx = fmaxf(mx, B[c*NM*NG + m*NG + g]);
        float s = 0.f;
        #pragma unroll
        for (int m = 0; m < NM; m++) s += expf(B[c*NM*NG + m*NG + g] - mx);
        float rs = 1.f / s;
        #pragma unroll
        for (int m = 0; m < NM; m++)
            g_smBf[m*NG*NC + g*NC + c] = expf(B[c*NM*NG + m*NG + g] - mx) * rs;
    }
    if (tid < NG) {   // Pi: softmax over c for each g
        int gg = tid;
        float mx = -1e30f;
        #pragma unroll
        for (int cc = 0; cc < NC; cc++) mx = fmaxf(mx, Pi[cc*NG + gg]);
        float s = 0.f;
        #pragma unroll
        for (int cc = 0; cc < NC; cc++) s += expf(Pi[cc*NG + gg] - mx);
        float rs = 1.f / s;
        #pragma unroll
        for (int cc = 0; cc < NC; cc++)
            g_smPi[cc*NG + gg] = expf(Pi[cc*NG + gg] - mx) * rs;
    }
    __syncthreads();
    // per (m,g): nu = sum_c Pi*B ; leaf beta = Pi*B/nu (half) ; log2 nu
    for (int i = tid; i < NM*NG; i += 256) {
        int m = i >> 4, gg = i & 15;
        float v[NC]; float nu = 0.f;
        #pragma unroll
        for (int cc = 0; cc < NC; cc++) {
            v[cc] = g_smPi[cc*NG + gg] * g_smBf[m*NG*NC + gg*NC + cc];
            nu += v[cc];
        }
        float rnu = 1.f / nu;
        #pragma unroll
        for (int cc = 0; cc < NC; cc++)
            g_leafH[m*NG*NC + gg*NC + cc] = __float2half_rn(v[cc] * rnu);
        g_nuLog[i] = log2f(nu);
    }
}

// ---------------------------------------------------------------------------
// Main kernel: one CTA per tree, 2 CTAs/SM. R4 skeleton.
// pblk = tid&3 (states p = 4*pblk..+3), g = (tid>>2)&15, ng = tid>>6.
// Per parent k: compute both sibling betas jointly; single rcp+log per pair:
//   beta0+beta1 = (s1*bv0 + s0*bv1) / (s0*s1),  ll += log2(s0*s1).
// ---------------------------------------------------------------------------
__global__ void __launch_bounds__(256, 2)
htmm_upward_kernel(const int* __restrict__ x, float* __restrict__ out) {
    extern __shared__ __align__(16) float sm[];
    float*  sW   = sm;                                  // 48*256 floats
    float*  sBf  = sm + W_FLOATS;                       // [m][g][c] fp32
    __half* sLf  = (__half*)(sm + W_FLOATS + BF_FLOATS);        // [m][g(pad20)][c]
    float*  sNuL = (float*)((char*)sLf + LEAF_HALFS*2);         // [m][g]
    __shared__ int   sx[NPT];
    __shared__ float sacc[256];

    const int tid  = threadIdx.x;
    const int pblk = tid & 3;
    const int g    = (tid >> 2) & 15;
    const int ng   = tid >> 6;

    // ---- stage tables (A via sW scratch; consumed into regs before leaves) ----
    for (int i = tid; i < NC*NC*NG; i += 256) sW[i]  = g_smA[i];
    for (int i = tid; i < BF_FLOATS; i += 256) sBf[i] = g_smBf[i];
    for (int i = tid; i < NM*NG*NC; i += 256) {
        int m = i >> 8, r = i & 255;                    // r = g*16 + c
        sLf[m*(NG*LSTR) + (r >> 4)*LSTR + (r & 15)] = g_leafH[i];
    }
    for (int i = tid; i < NM*NG; i += 256) sNuL[i] = g_nuLog[i];
    for (int i = tid; i < NPT; i += 256)   sx[i]  = x[blockIdx.x*NPT + i];
    __syncthreads();

    // A packed along c-pairs for this thread's states p = 4*pblk+ip
    ull A2[4][8];
    #pragma unroll
    for (int ip = 0; ip < 4; ip++) {
        int p = 4*pblk + ip;
        #pragma unroll
        for (int c2 = 0; c2 < 8; c2++)
            A2[ip][c2] = pack2(sW[p*256 + (2*c2)*16 + g],
                               sW[p*256 + (2*c2+1)*16 + g]);
    }
    __syncthreads();   // sW scratch may now be overwritten

    float accll = 0.f;   // accumulated in log2 units

    // ---- Level 6 (leaves fused): parents k in [0,32), siblings j=2k,2k+1 ----
    for (int k = ng; k < 32; k += 4) {
        float s_[2]; float bvp[2][4];
        #pragma unroll
        for (int sel = 0; sel < 2; sel++) {
            const int j  = 2*k + sel;                   // level-6 node
            const int m0 = sx[127 + 2*j], m1 = sx[128 + 2*j];
            const unsigned* L0 = (const unsigned*)(sLf + m0*(NG*LSTR) + g*LSTR);
            const unsigned* L1 = (const unsigned*)(sLf + m1*(NG*LSTR) + g*LSTR);
            ull a0 = 0ull, a1 = 0ull, a2 = 0ull, a3 = 0ull;
            #pragma unroll
            for (int c4 = 0; c4 < 4; c4++) {
                uint2 h0 = *(const uint2*)(L0 + 2*c4);  // 4 halfs of leaf-beta(m0)
                uint2 h1 = *(const uint2*)(L1 + 2*c4);  // 4 halfs of leaf-beta(m1)
                ull w = h2sum_to_f32x2(h0.x, h1.x);     // beta0+beta1, c = 4c4,4c4+1
                ffma2(a0, A2[0][2*c4], w);
                ffma2(a1, A2[1][2*c4], w);
                ffma2(a2, A2[2][2*c4], w);
                ffma2(a3, A2[3][2*c4], w);
                ull v = h2sum_to_f32x2(h0.y, h1.y);     // c = 4c4+2, 4c4+3
                ffma2(a0, A2[0][2*c4+1], v);
                ffma2(a1, A2[1][2*c4+1], v);
                ffma2(a2, A2[2][2*c4+1], v);
                ffma2(a3, A2[3][2*c4+1], v);
            }
            accll += 0.25f * (sNuL[m0*NG + g] + sNuL[m1*NG + g]);  // leaf lls

            const int mu = sx[63 + j];
            const float4 e4 = *(const float4*)(sBf + mu*256 + g*16 + 4*pblk);
            bvp[sel][0] = e4.x * unpack_sum(a0);
            bvp[sel][1] = e4.y * unpack_sum(a1);
            bvp[sel][2] = e4.z * unpack_sum(a2);
            bvp[sel][3] = e4.w * unpack_sum(a3);
            float s = (bvp[sel][0] + bvp[sel][1]) + (bvp[sel][2] + bvp[sel][3]);
            s += __shfl_xor_sync(0xffffffffu, s, 1);
            s += __shfl_xor_sync(0xffffffffu, s, 2);
            s_[sel] = s;
        }
        const float prod = s_[0] * s_[1];
        const float r = __fdividef(1.f, prod);
        accll += 0.25f * __log2f(prod);                 // both level-6 node lls
        float4 wo;
        wo.x = fmaf(s_[1], bvp[0][0], s_[0]*bvp[1][0]) * r;
        wo.y = fmaf(s_[1], bvp[0][1], s_[0]*bvp[1][1]) * r;
        wo.z = fmaf(s_[1], bvp[0][2], s_[0]*bvp[1][2]) * r;
        wo.w = fmaf(s_[1], bvp[0][3], s_[0]*bvp[1][3]) * r;
        *(float4*)(sW + W_R0 + k*256 + g*16 + 4*pblk) = wo;
    }
    __syncthreads();

    // ---- Levels 5..1 ----
    #pragma unroll 1
    for (int l = 5; l >= 1; l--) {
        const int nPar   = 1 << (l - 1);
        const int rbase  = (l & 1) ? W_R0 : W_R1;   // written by level l+1
        const int wbase  = (l & 1) ? W_R1 : W_R0;
        const int lstart = (1 << l) - 1;
        for (int k = ng; k < nPar; k += 4) {
            float s_[2]; float bvp[2][4];
            #pragma unroll
            for (int sel = 0; sel < 2; sel++) {
                const int j = 2*k + sel;
                const ull* wv = (const ull*)(sW + rbase + j*256 + g*16);
                ull a0 = 0ull, a1 = 0ull, a2 = 0ull, a3 = 0ull;
                #pragma unroll
                for (int c2 = 0; c2 < 8; c2++) {
                    ull w = wv[c2];                  // beta_ch0+beta_ch1 pre-summed
                    ffma2(a0, A2[0][c2], w);
                    ffma2(a1, A2[1][c2], w);
                    ffma2(a2, A2[2][c2], w);
                    ffma2(a3, A2[3][c2], w);
                }
                const int mu = sx[lstart + j];
                const float4 e4 = *(const float4*)(sBf + mu*256 + g*16 + 4*pblk);
                bvp[sel][0] = e4.x * unpack_sum(a0);
                bvp[sel][1] = e4.y * unpack_sum(a1);
                bvp[sel][2] = e4.z * unpack_sum(a2);
                bvp[sel][3] = e4.w * unpack_sum(a3);
                float s = (bvp[sel][0] + bvp[sel][1]) + (bvp[sel][2] + bvp[sel][3]);
                s += __shfl_xor_sync(0xffffffffu, s, 1);
                s += __shfl_xor_sync(0xffffffffu, s, 2);
                s_[sel] = s;
            }
            // true nu = s/2 per node; /2 cancels in normalization, -1 folded at end
            const float prod = s_[0] * s_[1];
            const float r = __fdividef(1.f, prod);
            accll += 0.25f * __log2f(prod);
            float4 wo;
            wo.x = fmaf(s_[1], bvp[0][0], s_[0]*bvp[1][0]) * r;
            wo.y = fmaf(s_[1], bvp[0][1], s_[0]*bvp[1][1]) * r;
            wo.z = fmaf(s_[1], bvp[0][2], s_[0]*bvp[1][2]) * r;
            wo.w = fmaf(s_[1], bvp[0][3], s_[0]*bvp[1][3]) * r;
            *(float4*)(sW + wbase + k*256 + g*16 + 4*pblk) = wo;
        }
        __syncthreads();
    }

    // ---- Root (level 0): group 0 only, ll contribution only ----
    if (ng == 0) {
        const ull* wv = (const ull*)(sW + W_R1 + g*16);   // level 1 wrote R1 slot 0
        ull a0 = 0ull, a1 = 0ull, a2 = 0ull, a3 = 0ull;
        #pragma unroll
        for (int c2 = 0; c2 < 8; c2++) {
            ull w = wv[c2];
            ffma2(a0, A2[0][c2], w);
            ffma2(a1, A2[1][c2], w);
            ffma2(a2, A2[2][c2], w);
            ffma2(a3, A2[3][c2], w);
        }
        const int mu = sx[0];
        const float4 e4 = *(const float4*)(sBf + mu*256 + g*16 + 4*pblk);
        float s = (e4.x*unpack_sum(a0) + e4.y*unpack_sum(a1))
                + (e4.z*unpack_sum(a2) + e4.w*unpack_sum(a3));
        s += __shfl_xor_sync(0xffffffffu, s, 1);
        s += __shfl_xor_sync(0xffffffffu, s, 2);
        accll += 0.25f * __log2f(s);
    }

    // ---- Deterministic per-g reduction over the 16 threads sharing g ----
    sacc[tid] = accll;
    __syncthreads();
    if (tid < NG) {
        float s = 0.f;
        #pragma unroll
        for (int kk = 0; kk < 16; kk++)
            s += sacc[(kk >> 2)*64 + tid*4 + (kk & 3)];
        // 127 internal nodes each owe -1 in log2 (folded BF=2 mean); convert to ln
        out[blockIdx.x*NG + tid] = 0.69314718055994530942f * (s - 127.0f);
    }
}

// ---------------------------------------------------------------------------
extern "C" void kernel_launch(void* const* d_in, const int* in_sizes, int n_in,
                              void* d_out, int out_size) {
    const float* A  = (const float*)d_in[0];
    const float* B  = (const float*)d_in[1];
    const float* Pi = (const float*)d_in[2];
    const int*   x  = (const int*)  d_in[3];
    float* out = (float*)d_out;

    cudaFuncSetAttribute(htmm_upward_kernel,
                         cudaFuncAttributeMaxDynamicSharedMemorySize, DYN_BYTES);

    htmm_softmax_kernel<<<1, 256>>>(A, B, Pi);
    htmm_upward_kernel<<<NT, 256, DYN_BYTES>>>(x, out);
}

// round 7
// speedup vs baseline: 1.2863x; 1.2863x over previous
#include <cuda_runtime.h>
#include <math.h>

#define NT 2000
#define NPT 255
#define NC 16
#define NM 32
#define NG 16
#define PGRID 296                     // persistent grid: 2 CTAs/SM x 148 SMs

typedef unsigned long long ull;

// dynamic shared layout (float offsets) — EXACT R4 layout
#define W_R0 0                        // 32 slots (written by levels 6,4,2)
#define W_R1 (32*256)                 // 16 slots (written by levels 5,3,1)
#define W_FLOATS (48*256)             // 48KB: child-pair-sum ping-pong
#define BF_FLOATS (NM*NG*NC)          // 32KB: softmaxed B, [m][g][c]
#define DYN_FLOATS (W_FLOATS + BF_FLOATS + NM*NG*2)
#define DYN_BYTES  (DYN_FLOATS*4)     // 86016 B -> 2 CTAs/SM

__device__ float  g_smA[NC*NC*NG];    // softmaxed A, [p][c][g]
__device__ float  g_smBf[NM*NG*NC];   // softmaxed B, [m][g][c]
__device__ float  g_smPi[NC*NG];      // softmaxed Pi, [c][g]
__device__ float2 g_nu[NM*NG];        // leaf {1/nu, log2 nu} per (m,g)

// ---------------------------------------------------------------------------
// packed f32x2 helpers (FFMA2/FMUL2 only reachable via PTX)
// ---------------------------------------------------------------------------
__device__ __forceinline__ ull pack2(float lo, float hi) {
    ull r; asm("mov.b64 %0, {%1, %2};" : "=l"(r) : "f"(lo), "f"(hi)); return r;
}
__device__ __forceinline__ void ffma2(ull& d, ull a, ull b) {
    asm("fma.rn.f32x2 %0, %1, %2, %0;" : "+l"(d) : "l"(a), "l"(b));
}
__device__ __forceinline__ void mul2(ull& d, ull a) {
    asm("mul.rn.f32x2 %0, %0, %1;" : "+l"(d) : "l"(a));
}
__device__ __forceinline__ float unpack_sum(ull v) {
    float lo, hi; asm("mov.b64 {%0, %1}, %2;" : "=f"(lo), "=f"(hi) : "l"(v));
    return lo + hi;
}

// ---------------------------------------------------------------------------
// Prologue: softmaxes + [m][g][c] B + leaf-nu table. 1 block, 256 threads.
// ---------------------------------------------------------------------------
__global__ void htmm_softmax_kernel(const float* __restrict__ A,
                                    const float* __restrict__ B,
                                    const float* __restrict__ Pi) {
    int tid = threadIdx.x;
    int c = tid >> 4;
    int g = tid & 15;
    {   // A: softmax over p for each (c,g)
        float mx = -1e30f;
        #pragma unroll
        for (int p = 0; p < NC; p++) mx = fmaxf(mx, A[p*NC*NG + c*NG + g]);
        float e[NC]; float s = 0.f;
        #pragma unroll
        for (int p = 0; p < NC; p++) { e[p] = expf(A[p*NC*NG + c*NG + g] - mx); s += e[p]; }
        float rs = 1.f / s;
        #pragma unroll
        for (int p = 0; p < NC; p++) g_smA[p*NC*NG + c*NG + g] = e[p] * rs;
    }
    {   // B: softmax over m for each (c,g); store [m][g][c]
        float mx = -1e30f;
        #pragma unroll
        for (int m = 0; m < NM; m++) mx = fmaxf(mx, B[c*NM*NG + m*NG + g]);
        float s = 0.f;
        #pragma unroll
        for (int m = 0; m < NM; m++) s += expf(B[c*NM*NG + m*NG + g] - mx);
        float rs = 1.f / s;
        #pragma unroll
        for (int m = 0; m < NM; m++)
            g_smBf[m*NG*NC + g*NC + c] = expf(B[c*NM*NG + m*NG + g] - mx) * rs;
    }
    if (tid < NG) {   // Pi: softmax over c for each g
        int gg = tid;
        float mx = -1e30f;
        #pragma unroll
        for (int cc = 0; cc < NC; cc++) mx = fmaxf(mx, Pi[cc*NG + gg]);
        float s = 0.f;
        #pragma unroll
        for (int cc = 0; cc < NC; cc++) s += expf(Pi[cc*NG + gg] - mx);
        float rs = 1.f / s;
        #pragma unroll
        for (int cc = 0; cc < NC; cc++)
            g_smPi[cc*NG + gg] = expf(Pi[cc*NG + gg] - mx) * rs;
    }
    __syncthreads();
    // leaf nu: nu(m,g) = sum_c Pi[c,g]*smB[c,m,g]; store {1/nu, log2 nu}
    for (int i = tid; i < NM*NG; i += 256) {
        int m = i >> 4, gg = i & 15;
        float nu = 0.f;
        #pragma unroll
        for (int cc = 0; cc < NC; cc++)
            nu += g_smPi[cc*NG + gg] * g_smBf[m*NG*NC + gg*NC + cc];
        g_nu[i] = make_float2(1.f / nu, log2f(nu));
    }
}

// ---------------------------------------------------------------------------
// Main kernel: PERSISTENT — grid 296, each CTA stages tables once and strides
// over trees. Hot loops identical to R4 (best-known schedule).
// pblk = tid&3 (states p = 4*pblk..+3), g = (tid>>2)&15, ng = tid>>6.
// Iterate over PARENTS: compute both sibling betas, store only their sum.
// ---------------------------------------------------------------------------
__global__ void __launch_bounds__(256, 2)
htmm_upward_kernel(const int* __restrict__ x, float* __restrict__ out) {
    extern __shared__ __align__(16) float sm[];
    float*  sW  = sm;                               // 48*256 floats
    float*  sBf = sm + W_FLOATS;                    // [m][g][c]
    float2* sNu = (float2*)(sm + W_FLOATS + BF_FLOATS);
    __shared__ int   sx[NPT];
    __shared__ float sacc[256];

    const int tid  = threadIdx.x;
    const int pblk = tid & 3;
    const int g    = (tid >> 2) & 15;
    const int ng   = tid >> 6;

    // ---- stage tables ONCE (A via sW scratch; consumed into regs) ----
    for (int i = tid; i < NC*NC*NG; i += 256) sW[i]  = g_smA[i];
    for (int i = tid; i < BF_FLOATS; i += 256) sBf[i] = g_smBf[i];
    for (int i = tid; i < NM*NG; i += 256)     sNu[i] = g_nu[i];
    __syncthreads();

    // A packed along c-pairs for this thread's states p = 4*pblk+ip
    ull A2[4][8];
    #pragma unroll
    for (int ip = 0; ip < 4; ip++) {
        int p = 4*pblk + ip;
        #pragma unroll
        for (int c2 = 0; c2 < 8; c2++)
            A2[ip][c2] = pack2(sW[p*256 + (2*c2)*16 + g],
                               sW[p*256 + (2*c2+1)*16 + g]);
    }
    ull Pi2[8];
    #pragma unroll
    for (int c2 = 0; c2 < 8; c2++)
        Pi2[c2] = pack2(g_smPi[(2*c2)*16 + g], g_smPi[(2*c2+1)*16 + g]);

    // ---- persistent tree loop ----
    for (int tree = blockIdx.x; tree < NT; tree += PGRID) {
        __syncthreads();   // protect sW/sx reuse from previous tree
        for (int i = tid; i < NPT; i += 256) sx[i] = x[tree*NPT + i];
        __syncthreads();

        float accll = 0.f;   // log2 units

        // ---- Level 6 (leaves fused): parents k in [0,32) ----
        for (int k = ng; k < 32; k += 4) {
            float wo0 = 0.f, wo1 = 0.f, wo2 = 0.f, wo3 = 0.f;
            #pragma unroll
            for (int sel = 0; sel < 2; sel++) {
                const int j  = 2*k + sel;                  // level-6 node
                const int m0 = sx[127 + 2*j], m1 = sx[128 + 2*j];
                const float2 n0 = sNu[m0*NG + g], n1 = sNu[m1*NG + g];
                const ull r0 = pack2(n0.x, n0.x);
                const ull r1 = pack2(n1.x, n1.x);
                const ull* b0 = (const ull*)(sBf + m0*256 + g*16);
                const ull* b1 = (const ull*)(sBf + m1*256 + g*16);
                ull a0 = 0ull, a1 = 0ull, a2 = 0ull, a3 = 0ull;
                #pragma unroll
                for (int c2 = 0; c2 < 8; c2++) {
                    ull w = b0[c2];
                    mul2(w, r0);                 // B(m0)/nu0
                    ffma2(w, b1[c2], r1);        // + B(m1)/nu1
                    mul2(w, Pi2[c2]);            // * Pi  = beta_leaf0 + beta_leaf1
                    ffma2(a0, A2[0][c2], w);
                    ffma2(a1, A2[1][c2], w);
                    ffma2(a2, A2[2][c2], w);
                    ffma2(a3, A2[3][c2], w);
                }
                accll += 0.25f * (n0.y + n1.y);            // leaf lls (log2)

                const int mu = sx[63 + j];
                const float4 e4 = *(const float4*)(sBf + mu*256 + g*16 + 4*pblk);
                float bv0 = e4.x * unpack_sum(a0);
                float bv1 = e4.y * unpack_sum(a1);
                float bv2 = e4.z * unpack_sum(a2);
                float bv3 = e4.w * unpack_sum(a3);
                float s = (bv0 + bv1) + (bv2 + bv3);
                s += __shfl_xor_sync(0xffffffffu, s, 1);
                s += __shfl_xor_sync(0xffffffffu, s, 2);
                float rs = __fdividef(1.f, s);
                wo0 += bv0*rs; wo1 += bv1*rs; wo2 += bv2*rs; wo3 += bv3*rs;
                accll += 0.25f * __log2f(s);
            }
            *(float4*)(sW + W_R0 + k*256 + g*16 + 4*pblk) =
                make_float4(wo0, wo1, wo2, wo3);
        }
        __syncthreads();

        // ---- Levels 5..1 ----
        #pragma unroll 1
        for (int l = 5; l >= 1; l--) {
            const int nPar   = 1 << (l - 1);
            const int rbase  = (l & 1) ? W_R0 : W_R1;   // written by level l+1
            const int wbase  = (l & 1) ? W_R1 : W_R0;
            const int lstart = (1 << l) - 1;
            for (int k = ng; k < nPar; k += 4) {
                float wo0 = 0.f, wo1 = 0.f, wo2 = 0.f, wo3 = 0.f;
                #pragma unroll
                for (int sel = 0; sel < 2; sel++) {
                    const int j = 2*k + sel;
                    const ull* wv = (const ull*)(sW + rbase + j*256 + g*16);
                    ull a0 = 0ull, a1 = 0ull, a2 = 0ull, a3 = 0ull;
                    #pragma unroll
                    for (int c2 = 0; c2 < 8; c2++) {
                        ull w = wv[c2];                  // pre-summed sibling pair
                        ffma2(a0, A2[0][c2], w);
                        ffma2(a1, A2[1][c2], w);
                        ffma2(a2, A2[2][c2], w);
                        ffma2(a3, A2[3][c2], w);
                    }
                    const int mu = sx[lstart + j];
                    const float4 e4 = *(const float4*)(sBf + mu*256 + g*16 + 4*pblk);
                    float bv0 = e4.x * unpack_sum(a0);
                    float bv1 = e4.y * unpack_sum(a1);
                    float bv2 = e4.z * unpack_sum(a2);
                    float bv3 = e4.w * unpack_sum(a3);
                    float s = (bv0 + bv1) + (bv2 + bv3);
                    s += __shfl_xor_sync(0xffffffffu, s, 1);
                    s += __shfl_xor_sync(0xffffffffu, s, 2);
                    // true nu = s/2; /2 cancels in normalization, -1 folded at end
                    float rs = __fdividef(1.f, s);
                    wo0 += bv0*rs; wo1 += bv1*rs; wo2 += bv2*rs; wo3 += bv3*rs;
                    accll += 0.25f * __log2f(s);
                }
                *(float4*)(sW + wbase + k*256 + g*16 + 4*pblk) =
                    make_float4(wo0, wo1, wo2, wo3);
            }
            __syncthreads();
        }

        // ---- Root (level 0): group 0 only, ll contribution only ----
        if (ng == 0) {
            const ull* wv = (const ull*)(sW + W_R1 + g*16);   // level 1 wrote R1 slot 0
            ull a0 = 0ull, a1 = 0ull, a2 = 0ull, a3 = 0ull;
            #pragma unroll
            for (int c2 = 0; c2 < 8; c2++) {
                ull w = wv[c2];
                ffma2(a0, A2[0][c2], w);
                ffma2(a1, A2[1][c2], w);
                ffma2(a2, A2[2][c2], w);
                ffma2(a3, A2[3][c2], w);
            }
            const int mu = sx[0];
            const float4 e4 = *(const float4*)(sBf + mu*256 + g*16 + 4*pblk);
            float s = (e4.x*unpack_sum(a0) + e4.y*unpack_sum(a1))
                    + (e4.z*unpack_sum(a2) + e4.w*unpack_sum(a3));
            s += __shfl_xor_sync(0xffffffffu, s, 1);
            s += __shfl_xor_sync(0xffffffffu, s, 2);
            accll += 0.25f * __log2f(s);
        }

        // ---- Deterministic per-g reduction over the 16 threads sharing g ----
        sacc[tid] = accll;
        __syncthreads();
        if (tid < NG) {
            float s = 0.f;
            #pragma unroll
            for (int kk = 0; kk < 16; kk++)
                s += sacc[(kk >> 2)*64 + tid*4 + (kk & 3)];
            // 127 internal nodes owe -1 each in log2 (folded BF=2 mean); to ln
            out[tree*NG + tid] = 0.69314718055994530942f * (s - 127.0f);
        }
    }
}

// ---------------------------------------------------------------------------
extern "C" void kernel_launch(void* const* d_in, const int* in_sizes, int n_in,
                              void* d_out, int out_size) {
    const float* A  = (const float*)d_in[0];
    const float* B  = (const float*)d_in[1];
    const float* Pi = (const float*)d_in[2];
    const int*   x  = (const int*)  d_in[3];
    float* out = (float*)d_out;

    cudaFuncSetAttribute(htmm_upward_kernel,
                         cudaFuncAttributeMaxDynamicSharedMemorySize, DYN_BYTES);

    htmm_softmax_kernel<<<1, 256>>>(A, B, Pi);
    htmm_upward_kernel<<<PGRID, 256, DYN_BYTES>>>(x, out);
}

// round 8
// speedup vs baseline: 1.2890x; 1.0021x over previous
#include <cuda_runtime.h>
#include <math.h>

#define NT 2000
#define NPT 255
#define NC 16
#define NM 32
#define NG 16
#define PGRID 296                     // persistent grid: 2 CTAs/SM x 148 SMs

typedef unsigned long long ull;

// dynamic shared layout (float offsets)
#define W_FLOATS (32*256)             // 32KB: in-place pairsum slots (stride-doubling)
#define BF_FLOATS (NM*NG*NC)          // 32KB: emission table [m][g][c]
#define PB_FLOATS (NM*NG*NC)          // 32KB: normalized leaf beta Pi*B/nu, [m][g][c]
#define DYN_FLOATS (W_FLOATS + BF_FLOATS + PB_FLOATS + NM*NG)
#define DYN_BYTES  (DYN_FLOATS*4)     // 100352 B -> 2 CTAs/SM

__device__ float g_smA[NC*NC*NG];     // softmaxed A, [p][c][g]
__device__ float g_smBf[NM*NG*NC];    // softmaxed B, [m][g][c]
__device__ float g_smPi[NC*NG];       // softmaxed Pi, [c][g]
__device__ float g_PiBn[NM*NG*NC];    // normalized leaf beta, [m][g][c]
__device__ float g_nuLog[NM*NG];      // log2 nu per (m,g)

// ---------------------------------------------------------------------------
// packed f32x2 helpers (FFMA2/FADD2 only reachable via PTX)
// ---------------------------------------------------------------------------
__device__ __forceinline__ ull pack2(float lo, float hi) {
    ull r; asm("mov.b64 %0, {%1, %2};" : "=l"(r) : "f"(lo), "f"(hi)); return r;
}
__device__ __forceinline__ void ffma2(ull& d, ull a, ull b) {
    asm("fma.rn.f32x2 %0, %1, %2, %0;" : "+l"(d) : "l"(a), "l"(b));
}
__device__ __forceinline__ void fadd2(ull& d, ull a) {
    asm("add.rn.f32x2 %0, %0, %1;" : "+l"(d) : "l"(a));
}
__device__ __forceinline__ float unpack_sum(ull v) {
    float lo, hi; asm("mov.b64 {%0, %1}, %2;" : "=f"(lo), "=f"(hi) : "l"(v));
    return lo + hi;
}

// ---------------------------------------------------------------------------
// Prologue: softmaxes + emission table + normalized leaf table + log2 nu.
// 1 block, 256 threads.
// ---------------------------------------------------------------------------
__global__ void htmm_softmax_kernel(const float* __restrict__ A,
                                    const float* __restrict__ B,
                                    const float* __restrict__ Pi) {
    int tid = threadIdx.x;
    int c = tid >> 4;
    int g = tid & 15;
    {   // A: softmax over p for each (c,g)
        float mx = -1e30f;
        #pragma unroll
        for (int p = 0; p < NC; p++) mx = fmaxf(mx, A[p*NC*NG + c*NG + g]);
        float e[NC]; float s = 0.f;
        #pragma unroll
        for (int p = 0; p < NC; p++) { e[p] = expf(A[p*NC*NG + c*NG + g] - mx); s += e[p]; }
        float rs = 1.f / s;
        #pragma unroll
        for (int p = 0; p < NC; p++) g_smA[p*NC*NG + c*NG + g] = e[p] * rs;
    }
    {   // B: softmax over m for each (c,g); store [m][g][c]
        float mx = -1e30f;
        #pragma unroll
        for (int m = 0; m < NM; m++) mx = fmaxf(mx, B[c*NM*NG + m*NG + g]);
        float s = 0.f;
        #pragma unroll
        for (int m = 0; m < NM; m++) s += expf(B[c*NM*NG + m*NG + g] - mx);
        float rs = 1.f / s;
        #pragma unroll
        for (int m = 0; m < NM; m++)
            g_smBf[m*NG*NC + g*NC + c] = expf(B[c*NM*NG + m*NG + g] - mx) * rs;
    }
    if (tid < NG) {   // Pi: softmax over c for each g
        int gg = tid;
        float mx = -1e30f;
        #pragma unroll
        for (int cc = 0; cc < NC; cc++) mx = fmaxf(mx, Pi[cc*NG + gg]);
        float s = 0.f;
        #pragma unroll
        for (int cc = 0; cc < NC; cc++) s += expf(Pi[cc*NG + gg] - mx);
        float rs = 1.f / s;
        #pragma unroll
        for (int cc = 0; cc < NC; cc++)
            g_smPi[cc*NG + gg] = expf(Pi[cc*NG + gg] - mx) * rs;
    }
    __syncthreads();
    // per (m,g): v = Pi*B; nu = sum v; PiBn = v/nu; log2 nu
    for (int i = tid; i < NM*NG; i += 256) {
        int m = i >> 4, gg = i & 15;
        float v[NC]; float nu = 0.f;
        #pragma unroll
        for (int cc = 0; cc < NC; cc++) {
            v[cc] = g_smPi[cc*NG + gg] * g_smBf[m*NG*NC + gg*NC + cc];
            nu += v[cc];
        }
        float rnu = 1.f / nu;
        #pragma unroll
        for (int cc = 0; cc < NC; cc++)
            g_PiBn[m*NG*NC + gg*NC + cc] = v[cc] * rnu;
        g_nuLog[i] = log2f(nu);
    }
}

// ---------------------------------------------------------------------------
// Main kernel: PERSISTENT — grid 296, tables staged once. R7 hot-loop skeleton;
// level 6 pairsum is now one FADD2 per c-pair (PiBn table), and the pairsum
// region is in-place with stride doubling:
//   level l (5..1): reads slots (2k+sel)*2^(5-l), writes slot 2k*2^(5-l).
// pblk = tid&3 (states p = 4*pblk..+3), g = (tid>>2)&15, ng = tid>>6.
// ---------------------------------------------------------------------------
__global__ void __launch_bounds__(256, 2)
htmm_upward_kernel(const int* __restrict__ x, float* __restrict__ out) {
    extern __shared__ __align__(16) float sm[];
    float* sW   = sm;                                   // 32*256 floats, in-place
    float* sBf  = sm + W_FLOATS;                        // [m][g][c]
    float* sPB  = sm + W_FLOATS + BF_FLOATS;            // [m][g][c]
    float* sNuL = sm + W_FLOATS + BF_FLOATS + PB_FLOATS;// [m*NG+g]
    __shared__ int   sx[NPT];
    __shared__ float sacc[256];

    const int tid  = threadIdx.x;
    const int pblk = tid & 3;
    const int g    = (tid >> 2) & 15;
    const int ng   = tid >> 6;

    // ---- stage tables ONCE (A via sW scratch; consumed into regs) ----
    for (int i = tid; i < NC*NC*NG; i += 256) sW[i]  = g_smA[i];
    for (int i = tid; i < BF_FLOATS; i += 256) sBf[i] = g_smBf[i];
    for (int i = tid; i < PB_FLOATS; i += 256) sPB[i] = g_PiBn[i];
    for (int i = tid; i < NM*NG; i += 256)     sNuL[i] = g_nuLog[i];
    __syncthreads();

    // A packed along c-pairs for this thread's states p = 4*pblk+ip
    ull A2[4][8];
    #pragma unroll
    for (int ip = 0; ip < 4; ip++) {
        int p = 4*pblk + ip;
        #pragma unroll
        for (int c2 = 0; c2 < 8; c2++)
            A2[ip][c2] = pack2(sW[p*256 + (2*c2)*16 + g],
                               sW[p*256 + (2*c2+1)*16 + g]);
    }

    // ---- persistent tree loop ----
    for (int tree = blockIdx.x; tree < NT; tree += PGRID) {
        __syncthreads();   // protect sW/sx reuse from previous tree
        for (int i = tid; i < NPT; i += 256) sx[i] = x[tree*NPT + i];
        __syncthreads();

        float accll = 0.f;   // log2 units

        // ---- Level 6 (leaves fused): parents k in [0,32) -> slot k ----
        for (int k = ng; k < 32; k += 4) {
            float wo0 = 0.f, wo1 = 0.f, wo2 = 0.f, wo3 = 0.f;
            #pragma unroll
            for (int sel = 0; sel < 2; sel++) {
                const int j  = 2*k + sel;                  // level-6 node
                const int m0 = sx[127 + 2*j], m1 = sx[128 + 2*j];
                const ull* b0 = (const ull*)(sPB + m0*256 + g*16);
                const ull* b1 = (const ull*)(sPB + m1*256 + g*16);
                ull a0 = 0ull, a1 = 0ull, a2 = 0ull, a3 = 0ull;
                #pragma unroll
                for (int c2 = 0; c2 < 8; c2++) {
                    ull w = b0[c2];
                    fadd2(w, b1[c2]);            // beta_leaf0 + beta_leaf1 (exact)
                    ffma2(a0, A2[0][c2], w);
                    ffma2(a1, A2[1][c2], w);
                    ffma2(a2, A2[2][c2], w);
                    ffma2(a3, A2[3][c2], w);
                }
                accll += 0.25f * (sNuL[m0*NG + g] + sNuL[m1*NG + g]);  // leaf lls

                const int mu = sx[63 + j];
                const float4 e4 = *(const float4*)(sBf + mu*256 + g*16 + 4*pblk);
                float bv0 = e4.x * unpack_sum(a0);
                float bv1 = e4.y * unpack_sum(a1);
                float bv2 = e4.z * unpack_sum(a2);
                float bv3 = e4.w * unpack_sum(a3);
                float s = (bv0 + bv1) + (bv2 + bv3);
                s += __shfl_xor_sync(0xffffffffu, s, 1);
                s += __shfl_xor_sync(0xffffffffu, s, 2);
                float rs = __fdividef(1.f, s);
                wo0 += bv0*rs; wo1 += bv1*rs; wo2 += bv2*rs; wo3 += bv3*rs;
                accll += 0.25f * __log2f(s);
            }
            *(float4*)(sW + k*256 + g*16 + 4*pblk) =
                make_float4(wo0, wo1, wo2, wo3);
        }
        __syncthreads();

        // ---- Levels 5..1 (in-place, stride doubling) ----
        #pragma unroll 1
        for (int l = 5; l >= 1; l--) {
            const int nPar   = 1 << (l - 1);
            const int st     = 1 << (5 - l);        // input slot stride
            const int lstart = (1 << l) - 1;
            for (int k = ng; k < nPar; k += 4) {
                float wo0 = 0.f, wo1 = 0.f, wo2 = 0.f, wo3 = 0.f;
                #pragma unroll
                for (int sel = 0; sel < 2; sel++) {
                    const int j = 2*k + sel;
                    const ull* wv = (const ull*)(sW + j*st*256 + g*16);
                    ull a0 = 0ull, a1 = 0ull, a2 = 0ull, a3 = 0ull;
                    #pragma unroll
                    for (int c2 = 0; c2 < 8; c2++) {
                        ull w = wv[c2];                  // pre-summed sibling pair
                        ffma2(a0, A2[0][c2], w);
                        ffma2(a1, A2[1][c2], w);
                        ffma2(a2, A2[2][c2], w);
                        ffma2(a3, A2[3][c2], w);
                    }
                    const int mu = sx[lstart + j];
                    const float4 e4 = *(const float4*)(sBf + mu*256 + g*16 + 4*pblk);
                    float bv0 = e4.x * unpack_sum(a0);
                    float bv1 = e4.y * unpack_sum(a1);
                    float bv2 = e4.z * unpack_sum(a2);
                    float bv3 = e4.w * unpack_sum(a3);
                    float s = (bv0 + bv1) + (bv2 + bv3);
                    s += __shfl_xor_sync(0xffffffffu, s, 1);
                    s += __shfl_xor_sync(0xffffffffu, s, 2);
                    // true nu = s/2; /2 cancels in normalization, -1 folded at end
                    float rs = __fdividef(1.f, s);
                    wo0 += bv0*rs; wo1 += bv1*rs; wo2 += bv2*rs; wo3 += bv3*rs;
                    accll += 0.25f * __log2f(s);
                }
                *(float4*)(sW + 2*k*st*256 + g*16 + 4*pblk) =
                    make_float4(wo0, wo1, wo2, wo3);
            }
            __syncthreads();
        }

        // ---- Root (level 0): group 0 only; level 1 wrote slot 0 ----
        if (ng == 0) {
            const ull* wv = (const ull*)(sW + g*16);
            ull a0 = 0ull, a1 = 0ull, a2 = 0ull, a3 = 0ull;
            #pragma unroll
            for (int c2 = 0; c2 < 8; c2++) {
                ull w = wv[c2];
                ffma2(a0, A2[0][c2], w);
                ffma2(a1, A2[1][c2], w);
                ffma2(a2, A2[2][c2], w);
                ffma2(a3, A2[3][c2], w);
            }
            const int mu = sx[0];
            const float4 e4 = *(const float4*)(sBf + mu*256 + g*16 + 4*pblk);
            float s = (e4.x*unpack_sum(a0) + e4.y*unpack_sum(a1))
                    + (e4.z*unpack_sum(a2) + e4.w*unpack_sum(a3));
            s += __shfl_xor_sync(0xffffffffu, s, 1);
            s += __shfl_xor_sync(0xffffffffu, s, 2);
            accll += 0.25f * __log2f(s);
        }

        // ---- Deterministic per-g reduction over the 16 threads sharing g ----
        sacc[tid] = accll;
        __syncthreads();
        if (tid < NG) {
            float s = 0.f;
            #pragma unroll
            for (int kk = 0; kk < 16; kk++)
                s += sacc[(kk >> 2)*64 + tid*4 + (kk & 3)];
            // 127 internal nodes owe -1 each in log2 (folded BF=2 mean); to ln
            out[tree*NG + tid] = 0.69314718055994530942f * (s - 127.0f);
        }
    }
}

// ---------------------------------------------------------------------------
extern "C" void kernel_launch(void* const* d_in, const int* in_sizes, int n_in,
                              void* d_out, int out_size) {
    const float* A  = (const float*)d_in[0];
    const float* B  = (const float*)d_in[1];
    const float* Pi = (const float*)d_in[2];
    const int*   x  = (const int*)  d_in[3];
    float* out = (float*)d_out;

    cudaFuncSetAttribute(htmm_upward_kernel,
                         cudaFuncAttributeMaxDynamicSharedMemorySize, DYN_BYTES);

    htmm_softmax_kernel<<<1, 256>>>(A, B, Pi);
    htmm_upward_kernel<<<PGRID, 256, DYN_BYTES>>>(x, out);
}